// round 10
// baseline (speedup 1.0000x reference)
#include <cuda_runtime.h>
#include <math.h>

#define BB 64
#define NN 1024
#define DDIM 1024
#define QKVN 512
#define HH 8
#define TK 32

#define NEG_INF (-3.402823466e38f)
#define FULLM 0xffffffffu

// packed fp32x2 FMA (FFMA2) — PTX-only, sm_100+
#define FMA2(d, a, b, c) \
    asm("fma.rn.f32x2 %0, %1, %2, %3;" : "=l"(d) : "l"(a), "l"(b), "l"(c))
#define UNPK2(lo, hi, v) \
    asm("mov.b64 {%0, %1}, %2;" : "=r"(lo), "=r"(hi) : "l"(v))

// ---------------- scratch (device globals, no allocation) ----------------
__device__ float g_logits[BB*NN];
__device__ float g_mean  [BB*NN];
__device__ float g_rstd  [BB*NN];
__device__ float g_biasg [BB*NN];
__device__ float g_stok  [BB*DDIM];
__device__ float g_sn    [BB*DDIM];
__device__ float g_query [BB*QKVN];
__device__ float g_skip  [BB*QKVN];
__device__ float g_w     [BB*HH*DDIM];
__device__ float g_sw    [BB*HH];
__device__ float g_cb    [BB*HH];
__device__ float g_scores[BB*HH*NN];
__device__ int   g_tki   [BB*HH*TK];
__device__ float g_alpha [BB*HH*TK];
__device__ float g_Am    [BB*HH];
__device__ float g_P     [BB*HH];
__device__ float g_Z     [BB*HH*DDIM];
__device__ float g_relu  [BB*QKVN];
__device__ float g_Mw    [2*QKVN];
__device__ float g_Mb    [2];

// ---------------- A: per-token logit + moments (pass 1 over x) ----------------
__global__ void __launch_bounds__(256) kA(const float* __restrict__ x,
                                          const float* __restrict__ sw,
                                          const float* __restrict__ sb) {
    __shared__ float s_w[1024];
    int tid = threadIdx.x;
#pragma unroll
    for (int i = 0; i < 4; i++) s_w[tid + i*256] = sw[tid + i*256];
    __syncthreads();
    int warp = tid >> 5, lane = tid & 31;
    int tok = blockIdx.x * 8 + warp;               // 0..65535
    const float* xr = x + (size_t)tok * 1024;
    float al = 0.f, asum = 0.f, ass = 0.f;
#pragma unroll
    for (int c = 0; c < 8; c++) {
        int d = c*128 + lane*4;
        float4 xv = *(const float4*)(xr + d);
        float4 wv = *(const float4*)(s_w + d);
        al = fmaf(xv.x, wv.x, al); al = fmaf(xv.y, wv.y, al);
        al = fmaf(xv.z, wv.z, al); al = fmaf(xv.w, wv.w, al);
        asum += xv.x + xv.y + xv.z + xv.w;
        ass = fmaf(xv.x,xv.x,ass); ass = fmaf(xv.y,xv.y,ass);
        ass = fmaf(xv.z,xv.z,ass); ass = fmaf(xv.w,xv.w,ass);
    }
#pragma unroll
    for (int o = 16; o > 0; o >>= 1) {
        al   += __shfl_xor_sync(FULLM, al,   o);
        asum += __shfl_xor_sync(FULLM, asum, o);
        ass  += __shfl_xor_sync(FULLM, ass,  o);
    }
    if (lane == 0) {
        float m = asum * (1.f/1024.f);
        float var = ass * (1.f/1024.f) - m*m;
        g_logits[tok] = al + sb[0];
        g_mean[tok]   = m;
        g_rstd[tok]   = rsqrtf(var + 1e-5f);
    }
}

// ------- B1: per-batch argmax, sel-token LN, positional-bias gather -------
__global__ void __launch_bounds__(256) kB1(const float* __restrict__ x,
                                           const float* __restrict__ gv,
                                           const float* __restrict__ bln,
                                           const float* __restrict__ ub,
                                           const int*   __restrict__ ridx) {
    __shared__ float sv[256];
    __shared__ int   si[256];
    __shared__ int   s_sel;
    int b = blockIdx.x, tid = threadIdx.x;
    float bv = NEG_INF; int bi = 0x7fffffff;
#pragma unroll
    for (int i = 0; i < 4; i++) {
        int n = tid*4 + i;
        float v = g_logits[b*1024 + n];
        if (v > bv || (v == bv && n < bi)) { bv = v; bi = n; }
    }
    sv[tid] = bv; si[tid] = bi;
    __syncthreads();
    for (int s = 128; s > 0; s >>= 1) {
        if (tid < s) {
            float ov = sv[tid+s]; int oi = si[tid+s];
            if (ov > sv[tid] || (ov == sv[tid] && oi < si[tid])) { sv[tid]=ov; si[tid]=oi; }
        }
        __syncthreads();
    }
    if (tid == 0) s_sel = si[0];
    __syncthreads();
    int sel = s_sel;
    float m = g_mean[b*1024 + sel], r = g_rstd[b*1024 + sel];
    const float* xr = x + ((size_t)b*1024 + sel)*1024;
#pragma unroll
    for (int i = 0; i < 4; i++) {
        int d = tid + i*256;
        float xv = xr[d];
        g_stok[b*1024 + d] = xv;
        g_sn  [b*1024 + d] = (xv - m)*r*gv[d] + bln[d];
    }
#pragma unroll
    for (int i = 0; i < 4; i++) {
        int n = tid + i*256;
        g_biasg[b*1024 + n] = ub[ridx[sel*1024 + n]];
    }
}

// ------- kQS: query AND skip GEMMs, one launch, f32x2 FMA, 3 blocks/SM -------
__global__ void __launch_bounds__(256, 3) kQS(const float* __restrict__ qkw,
                                              const float* __restrict__ qkb,
                                              const float* __restrict__ skw,
                                              const float* __restrict__ skb) {
    __shared__ float4 wr4[4*256];                 // 4 q-rows x 1024 floats
    int mode = blockIdx.x >> 9;
    int bid  = blockIdx.x & 511;
    const float* A    = mode ? g_stok : g_sn;
    const float* W    = mode ? skw    : qkw;
    const float* bias = mode ? skb    : qkb;
    float* C          = mode ? g_skip : g_query;
    int tid = threadIdx.x;
    int q0 = (bid >> 2) * 4;
    int bg = bid & 3;
    const float4* W4 = (const float4*)W;
#pragma unroll
    for (int r = 0; r < 4; r++) wr4[r*256 + tid] = W4[(size_t)(q0 + r)*256 + tid];
    __syncthreads();
    int warp = tid >> 5, lane = tid & 31;
#pragma unroll
    for (int s = 0; s < 2; s++) {
        int bb = bg*16 + warp*2 + s;
        const ulonglong2* A2 = (const ulonglong2*)(A + (size_t)bb*1024);
        unsigned long long c0 = 0ull, c1 = 0ull, c2 = 0ull, c3 = 0ull;
#pragma unroll
        for (int ch = 0; ch < 4; ch++) {
            ulonglong2 av[2];
#pragma unroll
            for (int i = 0; i < 2; i++) av[i] = A2[lane + (ch*2 + i)*32];
#pragma unroll
            for (int i = 0; i < 2; i++) {
                int col = lane + (ch*2 + i)*32;
                ulonglong2 w0 = *(const ulonglong2*)&wr4[0*256 + col];
                FMA2(c0, av[i].x, w0.x, c0); FMA2(c0, av[i].y, w0.y, c0);
                ulonglong2 w1 = *(const ulonglong2*)&wr4[1*256 + col];
                FMA2(c1, av[i].x, w1.x, c1); FMA2(c1, av[i].y, w1.y, c1);
                ulonglong2 w2 = *(const ulonglong2*)&wr4[2*256 + col];
                FMA2(c2, av[i].x, w2.x, c2); FMA2(c2, av[i].y, w2.y, c2);
                ulonglong2 w3 = *(const ulonglong2*)&wr4[3*256 + col];
                FMA2(c3, av[i].x, w3.x, c3); FMA2(c3, av[i].y, w3.y, c3);
            }
        }
        unsigned lo, hi;
        UNPK2(lo, hi, c0); float a0 = __uint_as_float(lo) + __uint_as_float(hi);
        UNPK2(lo, hi, c1); float a1 = __uint_as_float(lo) + __uint_as_float(hi);
        UNPK2(lo, hi, c2); float a2 = __uint_as_float(lo) + __uint_as_float(hi);
        UNPK2(lo, hi, c3); float a3 = __uint_as_float(lo) + __uint_as_float(hi);
#pragma unroll
        for (int o = 16; o > 0; o >>= 1) {
            a0 += __shfl_xor_sync(FULLM, a0, o);
            a1 += __shfl_xor_sync(FULLM, a1, o);
            a2 += __shfl_xor_sync(FULLM, a2, o);
            a3 += __shfl_xor_sync(FULLM, a3, o);
        }
        if (lane == 0) {
            C[bb*512 + q0 + 0] = a0 + bias[q0 + 0];
            C[bb*512 + q0 + 1] = a1 + bias[q0 + 1];
            C[bb*512 + q0 + 2] = a2 + bias[q0 + 2];
            C[bb*512 + q0 + 3] = a3 + bias[q0 + 3];
        }
    }
}

// ------- B34: u = qk_w_h^T q ; w = u*g/8 ; sw = sum(w) ; cb = (u.ln_b + q.qk_b)/8 -------
__global__ void __launch_bounds__(256) kB34(const float* __restrict__ qkw,
                                            const float* __restrict__ gv,
                                            const float* __restrict__ bln,
                                            const float* __restrict__ qkb) {
    int h = blockIdx.x & 7, b4 = blockIdx.x >> 3;    // grid 128
    __shared__ float qs[4][64];
    __shared__ float red[4][256];
    int tid = threadIdx.x;
    {
        int bb = tid >> 6, j = tid & 63;
        qs[bb][j] = g_query[(b4*4 + bb)*512 + h*64 + j];
    }
    __syncthreads();
    int d = tid * 4;
    float4 acc[4];
#pragma unroll
    for (int bb = 0; bb < 4; bb++) acc[bb] = make_float4(0.f,0.f,0.f,0.f);
#pragma unroll 4
    for (int j = 0; j < 64; j++) {
        float4 wv = *(const float4*)(qkw + (size_t)(h*64 + j)*1024 + d);
#pragma unroll
        for (int bb = 0; bb < 4; bb++) {
            float a = qs[bb][j];
            acc[bb].x = fmaf(wv.x, a, acc[bb].x);
            acc[bb].y = fmaf(wv.y, a, acc[bb].y);
            acc[bb].z = fmaf(wv.z, a, acc[bb].z);
            acc[bb].w = fmaf(wv.w, a, acc[bb].w);
        }
    }
    float4 gg = *(const float4*)(gv + d);
    float4 bl = *(const float4*)(bln + d);
    float swp[4], cbp[4];
#pragma unroll
    for (int bb = 0; bb < 4; bb++) {
        float4 w4v;
        w4v.x = acc[bb].x * gg.x * 0.125f;
        w4v.y = acc[bb].y * gg.y * 0.125f;
        w4v.z = acc[bb].z * gg.z * 0.125f;
        w4v.w = acc[bb].w * gg.w * 0.125f;
        *(float4*)(g_w + ((size_t)((b4*4 + bb)*8 + h))*1024 + d) = w4v;
        swp[bb] = w4v.x + w4v.y + w4v.z + w4v.w;
        float c = acc[bb].x*bl.x + acc[bb].y*bl.y + acc[bb].z*bl.z + acc[bb].w*bl.w;
        if (tid < 64) c = fmaf(qs[bb][tid], qkb[h*64 + tid], c);
        cbp[bb] = c;
    }
#pragma unroll
    for (int bb = 0; bb < 4; bb++) red[bb][tid] = swp[bb];
    __syncthreads();
    for (int s = 128; s > 0; s >>= 1) {
        if (tid < s) {
#pragma unroll
            for (int bb = 0; bb < 4; bb++) red[bb][tid] += red[bb][tid + s];
        }
        __syncthreads();
    }
    if (tid < 4) g_sw[(b4*4 + tid)*8 + h] = red[tid][0];
    __syncthreads();
#pragma unroll
    for (int bb = 0; bb < 4; bb++) red[bb][tid] = cbp[bb];
    __syncthreads();
    for (int s = 128; s > 0; s >>= 1) {
        if (tid < s) {
#pragma unroll
            for (int bb = 0; bb < 4; bb++) red[bb][tid] += red[bb][tid + s];
        }
        __syncthreads();
    }
    if (tid < 4) g_cb[(b4*4 + tid)*8 + h] = red[tid][0] * 0.125f;
}

// ------- C: big score pass; f32x2 packed FMA; butterfly reduce -------
__global__ void __launch_bounds__(256, 2) kC(const float* __restrict__ x) {
    int b = blockIdx.x >> 5, tc = blockIdx.x & 31;   // grid 2048
    __shared__ float ws[8192];                        // 8 heads x 1024 floats
    __shared__ float sm[32], sr[32], sb2[32], ssw[8], scb[8];
    int tid = threadIdx.x;
    {
        const float4* w4 = (const float4*)(g_w + (size_t)b*8192);
        float4* ws4 = (float4*)ws;
#pragma unroll
        for (int i = 0; i < 8; i++) ws4[tid + i*256] = w4[tid + i*256];
    }
    int n0 = tc * 32;
    if (tid < 32) {
        sm[tid]  = g_mean [b*1024 + n0 + tid];
        sr[tid]  = g_rstd [b*1024 + n0 + tid];
        sb2[tid] = g_biasg[b*1024 + n0 + tid];
    } else if (tid < 40) {
        ssw[tid-32] = g_sw[b*8 + tid-32];
        scb[tid-32] = g_cb[b*8 + tid-32];
    }
    __syncthreads();
    int warp = tid >> 5, lane = tid & 31;
    int t0 = n0 + warp*4;
    const ulonglong2* X2 = (const ulonglong2*)x + ((size_t)b*1024 + t0)*256;
    unsigned long long acc2[32];                      // acc2[h*4+tt] packed pair
#pragma unroll
    for (int i = 0; i < 32; i++) acc2[i] = 0ull;
#pragma unroll
    for (int c = 0; c < 8; c++) {
        ulonglong2 xv[4];
#pragma unroll
        for (int tt = 0; tt < 4; tt++) xv[tt] = X2[(size_t)tt*256 + lane + c*32];
#pragma unroll
        for (int h = 0; h < 8; h++) {
            ulonglong2 wv = *(const ulonglong2*)(ws + h*1024 + (lane + c*32)*4);
#pragma unroll
            for (int tt = 0; tt < 4; tt++) {
                FMA2(acc2[h*4 + tt], xv[tt].x, wv.x, acc2[h*4 + tt]);
                FMA2(acc2[h*4 + tt], xv[tt].y, wv.y, acc2[h*4 + tt]);
            }
        }
    }
    float vals[32];
#pragma unroll
    for (int i = 0; i < 32; i++) {
        unsigned lo, hi;
        UNPK2(lo, hi, acc2[i]);
        vals[i] = __uint_as_float(lo) + __uint_as_float(hi);
    }
    // multi-value butterfly: 32 values -> 1 per lane (index = bitrev5(lane))
#pragma unroll
    for (int s = 0; s < 5; s++) {
        int o = 1 << s;
        int nv = 32 >> s;
        int half = nv >> 1;
#pragma unroll
        for (int j = 0; j < 32; j++) {
            if (j < nv) vals[j] += __shfl_xor_sync(FULLM, vals[j], o);
        }
#pragma unroll
        for (int j = 0; j < 16; j++) {
            if (j < half) vals[j] = (lane & o) ? vals[j + half] : vals[j];
        }
    }
    int rev = ((lane & 1) << 4) | ((lane & 2) << 2) | (lane & 4)
            | ((lane & 8) >> 2) | ((lane & 16) >> 4);
    int h  = rev >> 2;
    int tt = rev & 3;
    int tloc = warp*4 + tt;
    float score = (vals[0] - sm[tloc]*ssw[h]) * sr[tloc] + scb[h] + sb2[tloc];
    g_scores[(size_t)(b*8 + h)*1024 + n0 + tloc] = score;
}

// ------- D: warp-per-(b,h) top-32 + softmax renorm, register-resident -------
__global__ void __launch_bounds__(256) kD() {
    int warp = threadIdx.x >> 5, lane = threadIdx.x & 31;
    int bh = blockIdx.x * 8 + warp;                  // grid 64
    const float* src = g_scores + (size_t)bh*1024;
    float v[32];
#pragma unroll
    for (int j = 0; j < 32; j++) v[j] = src[j*32 + lane];  // n = j*32 + lane
    unsigned taken = 0u;
    float cm = v[0]; int cj = 0;
#pragma unroll
    for (int j = 1; j < 32; j++) if (v[j] > cm) { cm = v[j]; cj = j; }
    float keep_v = NEG_INF; int keep_n = 0;
    for (int k = 0; k < 32; k++) {
        float m = cm; int mn = (cj << 5) | lane;
#pragma unroll
        for (int o = 16; o > 0; o >>= 1) {
            float om = __shfl_xor_sync(FULLM, m,  o);
            int   on = __shfl_xor_sync(FULLM, mn, o);
            if (om > m || (om == m && on < mn)) { m = om; mn = on; }
        }
        if (lane == k) { keep_v = m; keep_n = mn; }
        if ((mn & 31) == lane) taken |= 1u << (mn >> 5);
        cm = NEG_INF; cj = 0;
#pragma unroll
        for (int j = 0; j < 32; j++) {
            bool ok = ((taken >> j) & 1u) == 0u;
            if (ok && v[j] > cm) { cm = v[j]; cj = j; }
        }
    }
    float M = __shfl_sync(FULLM, keep_v, 0);
    float zs = 0.f;
#pragma unroll
    for (int j = 0; j < 32; j++) zs += expf(v[j] - M);
#pragma unroll
    for (int o = 16; o > 0; o >>= 1) zs += __shfl_xor_sync(FULLM, zs, o);
    float e = expf(keep_v - M);
    float Se = e;
#pragma unroll
    for (int o = 16; o > 0; o >>= 1) Se += __shfl_xor_sync(FULLM, Se, o);
    float p = e / (Se + 1e-9f * zs);
    int b = bh >> 3;
    float alpha = p * g_rstd[b*1024 + keep_n];
    g_tki  [bh*32 + lane] = keep_n;
    g_alpha[bh*32 + lane] = alpha;
    float Av = alpha * g_mean[b*1024 + keep_n];
    float Pv = p;
#pragma unroll
    for (int o = 16; o > 0; o >>= 1) {
        Av += __shfl_xor_sync(FULLM, Av, o);
        Pv += __shfl_xor_sync(FULLM, Pv, o);
    }
    if (lane == 0) { g_Am[bh] = Av; g_P[bh] = Pv; }
}

// ------- E1: z[b,h,:] = g*(sum_k alpha_k x[n_k] - A) + ln_b*P -------
__global__ void __launch_bounds__(256) kE1(const float* __restrict__ x,
                                           const float* __restrict__ gv,
                                           const float* __restrict__ bln) {
    int bh = blockIdx.x, b = bh >> 3;
    __shared__ int   sidx[32];
    __shared__ float sal [32];
    int tid = threadIdx.x;
    if (tid < 32) { sidx[tid] = g_tki[bh*32 + tid]; sal[tid] = g_alpha[bh*32 + tid]; }
    __syncthreads();
    int d = tid * 4;
    float4 acc = make_float4(0.f, 0.f, 0.f, 0.f);
#pragma unroll 8
    for (int k = 0; k < 32; k++) {
        float4 xv = *(const float4*)(x + ((size_t)(b*1024 + sidx[k]))*1024 + d);
        float a = sal[k];
        acc.x = fmaf(xv.x, a, acc.x);
        acc.y = fmaf(xv.y, a, acc.y);
        acc.z = fmaf(xv.z, a, acc.z);
        acc.w = fmaf(xv.w, a, acc.w);
    }
    float A = g_Am[bh], P = g_P[bh];
    float4 gg = *(const float4*)(gv + d);
    float4 bb = *(const float4*)(bln + d);
    float4 z;
    z.x = gg.x * (acc.x - A) + bb.x * P;
    z.y = gg.y * (acc.y - A) + bb.y * P;
    z.z = gg.z * (acc.z - A) + bb.z * P;
    z.w = gg.w * (acc.w - A) + bb.w * P;
    *(float4*)(g_Z + (size_t)bh*1024 + d) = z;
}

// ------- E2: y[b,h,j] = v_w_h[j].z[b,h] + v_b*P ; relu(+skip) -------
__global__ void __launch_bounds__(256) kE2(const float* __restrict__ vw,
                                           const float* __restrict__ vb) {
    int h = blockIdx.x & 7, g4 = blockIdx.x >> 3;    // grid 128
    __shared__ float zs[4][1024];
    __shared__ float sP[4];
    int tid = threadIdx.x;
    for (int i = tid; i < 4096; i += 256) {
        int bb = i >> 10, dd = i & 1023;
        zs[bb][dd] = g_Z[((size_t)((g4*4 + bb)*8 + h))*1024 + dd];
    }
    if (tid < 4) sP[tid] = g_P[(g4*4 + tid)*8 + h];
    __syncthreads();
    int warp = tid >> 5, lane = tid & 31;
#pragma unroll
    for (int t = 0; t < 8; t++) {
        int j = warp + t*8;
        const float* vr = vw + (size_t)(h*64 + j)*1024;
        float acc[4];
#pragma unroll
        for (int bb = 0; bb < 4; bb++) acc[bb] = 0.f;
#pragma unroll
        for (int c = 0; c < 8; c++) {
            int d = c*128 + lane*4;
            float4 wv = *(const float4*)(vr + d);
#pragma unroll
            for (int bb = 0; bb < 4; bb++) {
                float4 zv = *(const float4*)(&zs[bb][d]);
                acc[bb] = fmaf(wv.x, zv.x, acc[bb]);
                acc[bb] = fmaf(wv.y, zv.y, acc[bb]);
                acc[bb] = fmaf(wv.z, zv.z, acc[bb]);
                acc[bb] = fmaf(wv.w, zv.w, acc[bb]);
            }
        }
#pragma unroll
        for (int bb = 0; bb < 4; bb++)
#pragma unroll
            for (int o = 16; o > 0; o >>= 1)
                acc[bb] += __shfl_xor_sync(FULLM, acc[bb], o);
        if (lane == 0) {
            int q = h*64 + j;
            float vbq = vb[q];
#pragma unroll
            for (int bb = 0; bb < 4; bb++) {
                int b = g4*4 + bb;
                float y = acc[bb] + vbq * sP[bb] + g_skip[b*512 + q];
                g_relu[b*512 + q] = fmaxf(y, 0.f);
            }
        }
    }
}

// ------- Mw: fold out_w/fc_w: Mw[c][q] = sum_q' fc_w[c][q'] out_w[q'][q] -------
__global__ void __launch_bounds__(512) kMw(const float* __restrict__ ow,
                                           const float* __restrict__ ob,
                                           const float* __restrict__ fcw,
                                           const float* __restrict__ fcb) {
    int c = blockIdx.x;            // 2 blocks
    int q = threadIdx.x;           // 512 threads
    __shared__ float fr[512];
    __shared__ float red[512];
    fr[q] = fcw[c*512 + q];
    __syncthreads();
    float acc = 0.f;
#pragma unroll 8
    for (int qp = 0; qp < 512; qp++)
        acc = fmaf(fr[qp], ow[(size_t)qp*512 + q], acc);
    g_Mw[c*512 + q] = acc;
    red[q] = fr[q] * ob[q];
    __syncthreads();
    for (int s = 256; s > 0; s >>= 1) {
        if (q < s) red[q] += red[q+s];
        __syncthreads();
    }
    if (q == 0) g_Mb[c] = red[0] + fcb[c];
}

// ------- F: final [64,2] = relu @ Mw^T + Mb -------
__global__ void __launch_bounds__(128) kF(float* __restrict__ out) {
    int b = blockIdx.x, tid = threadIdx.x;     // 128 threads
    int warp = tid >> 5, lane = tid & 31;
    __shared__ float p0[4], p1[4];
    float s0 = 0.f, s1 = 0.f;
#pragma unroll
    for (int i = 0; i < 4; i++) {
        int q = tid + i*128;
        float rv = g_relu[b*512 + q];
        s0 = fmaf(rv, g_Mw[q],       s0);
        s1 = fmaf(rv, g_Mw[512 + q], s1);
    }
#pragma unroll
    for (int o = 16; o > 0; o >>= 1) {
        s0 += __shfl_xor_sync(FULLM, s0, o);
        s1 += __shfl_xor_sync(FULLM, s1, o);
    }
    if (lane == 0) { p0[warp] = s0; p1[warp] = s1; }
    __syncthreads();
    if (tid == 0) {
        out[b*2 + 0] = p0[0] + p0[1] + p0[2] + p0[3] + g_Mb[0];
        out[b*2 + 1] = p1[0] + p1[1] + p1[2] + p1[3] + g_Mb[1];
    }
}

extern "C" void kernel_launch(void* const* d_in, const int* in_sizes, int n_in,
                              void* d_out, int out_size) {
    const float* x        = (const float*)d_in[0];
    const float* scorer_w = (const float*)d_in[1];
    const float* scorer_b = (const float*)d_in[2];
    const float* ln_g     = (const float*)d_in[3];
    const float* ln_b     = (const float*)d_in[4];
    const float* qk_w     = (const float*)d_in[5];
    const float* qk_b     = (const float*)d_in[6];
    const float* v_w      = (const float*)d_in[7];
    const float* v_b      = (const float*)d_in[8];
    const float* skip_w   = (const float*)d_in[9];
    const float* skip_b   = (const float*)d_in[10];
    const float* out_w    = (const float*)d_in[11];
    const float* out_b    = (const float*)d_in[12];
    const float* fc_w     = (const float*)d_in[13];
    const float* fc_b     = (const float*)d_in[14];
    const float* ub       = (const float*)d_in[15];
    const int*   rel_idx  = (const int*)  d_in[16];
    float* out = (float*)d_out;
    (void)in_sizes; (void)n_in; (void)out_size;

    kMw <<<2,    512>>>(out_w, out_b, fc_w, fc_b);    // fused tail matrix
    kA  <<<8192, 256>>>(x, scorer_w, scorer_b);       // pass 1 over x
    kB1 <<<64,   256>>>(x, ln_g, ln_b, ub, rel_idx);
    kQS <<<1024, 256>>>(qk_w, qk_b, skip_w, skip_b);  // query + skip in one launch
    kB34<<<128,  256>>>(qk_w, ln_g, ln_b, qk_b);      // u -> w, sw, cb fused
    kC  <<<2048, 256>>>(x);                           // scores (pass 2 over x)
    kD  <<<64,   256>>>();                            // top-32 + softmax renorm
    kE1 <<<512,  256>>>(x, ln_g, ln_b);               // gathered z
    kE2 <<<128,  256>>>(v_w, v_b);                    // y = v_w.z, relu(+skip)
    kF  <<<64,   128>>>(out);                         // final [64,2]
}

// round 11
// speedup vs baseline: 1.1437x; 1.1437x over previous
#include <cuda_runtime.h>
#include <math.h>

#define BB 64
#define NN 1024
#define DDIM 1024
#define QKVN 512
#define HH 8
#define TK 32

#define NEG_INF (-3.402823466e38f)
#define FULLM 0xffffffffu

// ---------------- scratch (device globals, no allocation) ----------------
__device__ float g_logits[BB*NN];
__device__ float g_mean  [BB*NN];
__device__ float g_rstd  [BB*NN];
__device__ float g_biasg [BB*NN];
__device__ float g_stok  [BB*DDIM];
__device__ float g_sn    [BB*DDIM];
__device__ float g_query [BB*QKVN];
__device__ float g_skip  [BB*QKVN];
__device__ float g_w     [BB*HH*DDIM];
__device__ float g_sw    [BB*HH];
__device__ float g_cb    [BB*HH];
__device__ float g_scores[BB*HH*NN];
__device__ float g_Z     [BB*HH*DDIM];
__device__ float g_relu  [BB*QKVN];
__device__ float g_Mw    [2*QKVN];
__device__ float g_Mb    [2];

// ---------------- A: per-token logit + moments (pass 1 over x) ----------------
__global__ void __launch_bounds__(256) kA(const float* __restrict__ x,
                                          const float* __restrict__ sw,
                                          const float* __restrict__ sb) {
    __shared__ float s_w[1024];
    int tid = threadIdx.x;
#pragma unroll
    for (int i = 0; i < 4; i++) s_w[tid + i*256] = sw[tid + i*256];
    __syncthreads();
    int warp = tid >> 5, lane = tid & 31;
    int tok = blockIdx.x * 8 + warp;               // 0..65535
    const float* xr = x + (size_t)tok * 1024;
    float al = 0.f, asum = 0.f, ass = 0.f;
#pragma unroll
    for (int c = 0; c < 8; c++) {
        int d = c*128 + lane*4;
        float4 xv = *(const float4*)(xr + d);
        float4 wv = *(const float4*)(s_w + d);
        al = fmaf(xv.x, wv.x, al); al = fmaf(xv.y, wv.y, al);
        al = fmaf(xv.z, wv.z, al); al = fmaf(xv.w, wv.w, al);
        asum += xv.x + xv.y + xv.z + xv.w;
        ass = fmaf(xv.x,xv.x,ass); ass = fmaf(xv.y,xv.y,ass);
        ass = fmaf(xv.z,xv.z,ass); ass = fmaf(xv.w,xv.w,ass);
    }
#pragma unroll
    for (int o = 16; o > 0; o >>= 1) {
        al   += __shfl_xor_sync(FULLM, al,   o);
        asum += __shfl_xor_sync(FULLM, asum, o);
        ass  += __shfl_xor_sync(FULLM, ass,  o);
    }
    if (lane == 0) {
        float m = asum * (1.f/1024.f);
        float var = ass * (1.f/1024.f) - m*m;
        g_logits[tok] = al + sb[0];
        g_mean[tok]   = m;
        g_rstd[tok]   = rsqrtf(var + 1e-5f);
    }
}

// ------- B1: per-batch argmax, sel-token LN, positional-bias gather -------
__global__ void __launch_bounds__(256) kB1(const float* __restrict__ x,
                                           const float* __restrict__ gv,
                                           const float* __restrict__ bln,
                                           const float* __restrict__ ub,
                                           const int*   __restrict__ ridx) {
    __shared__ float sv[256];
    __shared__ int   si[256];
    __shared__ int   s_sel;
    int b = blockIdx.x, tid = threadIdx.x;
    float bv = NEG_INF; int bi = 0x7fffffff;
#pragma unroll
    for (int i = 0; i < 4; i++) {
        int n = tid*4 + i;
        float v = g_logits[b*1024 + n];
        if (v > bv || (v == bv && n < bi)) { bv = v; bi = n; }
    }
    sv[tid] = bv; si[tid] = bi;
    __syncthreads();
    for (int s = 128; s > 0; s >>= 1) {
        if (tid < s) {
            float ov = sv[tid+s]; int oi = si[tid+s];
            if (ov > sv[tid] || (ov == sv[tid] && oi < si[tid])) { sv[tid]=ov; si[tid]=oi; }
        }
        __syncthreads();
    }
    if (tid == 0) s_sel = si[0];
    __syncthreads();
    int sel = s_sel;
    float m = g_mean[b*1024 + sel], r = g_rstd[b*1024 + sel];
    const float* xr = x + ((size_t)b*1024 + sel)*1024;
#pragma unroll
    for (int i = 0; i < 4; i++) {
        int d = tid + i*256;
        float xv = xr[d];
        g_stok[b*1024 + d] = xv;
        g_sn  [b*1024 + d] = (xv - m)*r*gv[d] + bln[d];
    }
#pragma unroll
    for (int i = 0; i < 4; i++) {
        int n = tid + i*256;
        g_biasg[b*1024 + n] = ub[ridx[sel*1024 + n]];
    }
}

// ------- kQS: query AND skip GEMMs in one launch (grid 1024) — R8 version -------
__global__ void __launch_bounds__(256, 2) kQS(const float* __restrict__ qkw,
                                              const float* __restrict__ qkb,
                                              const float* __restrict__ skw,
                                              const float* __restrict__ skb) {
    __shared__ float4 wr4[4*256];                 // 4 q-rows x 1024 floats
    int mode = blockIdx.x >> 9;
    int bid  = blockIdx.x & 511;
    const float* A    = mode ? g_stok : g_sn;
    const float* W    = mode ? skw    : qkw;
    const float* bias = mode ? skb    : qkb;
    float* C          = mode ? g_skip : g_query;
    int tid = threadIdx.x;
    int q0 = (bid >> 2) * 4;
    int bg = bid & 3;
    const float4* W4 = (const float4*)W;
#pragma unroll
    for (int r = 0; r < 4; r++) wr4[r*256 + tid] = W4[(size_t)(q0 + r)*256 + tid];
    __syncthreads();
    int warp = tid >> 5, lane = tid & 31;
#pragma unroll
    for (int s = 0; s < 2; s++) {
        int bb = bg*16 + warp*2 + s;
        const float4* A4 = (const float4*)(A + (size_t)bb*1024);
        float a0 = 0.f, a1 = 0.f, a2 = 0.f, a3 = 0.f;
#pragma unroll
        for (int ch = 0; ch < 2; ch++) {
            float4 av[4];
#pragma unroll
            for (int i = 0; i < 4; i++) av[i] = A4[lane + (ch*4 + i)*32];
#pragma unroll
            for (int i = 0; i < 4; i++) {
                float4 a = av[i];
                int col = lane + (ch*4 + i)*32;
                float4 w0 = wr4[0*256 + col];
                a0 = fmaf(a.x,w0.x,a0); a0 = fmaf(a.y,w0.y,a0);
                a0 = fmaf(a.z,w0.z,a0); a0 = fmaf(a.w,w0.w,a0);
                float4 w1 = wr4[1*256 + col];
                a1 = fmaf(a.x,w1.x,a1); a1 = fmaf(a.y,w1.y,a1);
                a1 = fmaf(a.z,w1.z,a1); a1 = fmaf(a.w,w1.w,a1);
                float4 w2 = wr4[2*256 + col];
                a2 = fmaf(a.x,w2.x,a2); a2 = fmaf(a.y,w2.y,a2);
                a2 = fmaf(a.z,w2.z,a2); a2 = fmaf(a.w,w2.w,a2);
                float4 w3 = wr4[3*256 + col];
                a3 = fmaf(a.x,w3.x,a3); a3 = fmaf(a.y,w3.y,a3);
                a3 = fmaf(a.z,w3.z,a3); a3 = fmaf(a.w,w3.w,a3);
            }
        }
#pragma unroll
        for (int o = 16; o > 0; o >>= 1) {
            a0 += __shfl_xor_sync(FULLM, a0, o);
            a1 += __shfl_xor_sync(FULLM, a1, o);
            a2 += __shfl_xor_sync(FULLM, a2, o);
            a3 += __shfl_xor_sync(FULLM, a3, o);
        }
        if (lane == 0) {
            C[bb*512 + q0 + 0] = a0 + bias[q0 + 0];
            C[bb*512 + q0 + 1] = a1 + bias[q0 + 1];
            C[bb*512 + q0 + 2] = a2 + bias[q0 + 2];
            C[bb*512 + q0 + 3] = a3 + bias[q0 + 3];
        }
    }
}

// ------- B34: u = qk_w_h^T q ; w = u*g/8 ; sw = sum(w) ; cb = (u.ln_b + q.qk_b)/8 -------
__global__ void __launch_bounds__(256) kB34(const float* __restrict__ qkw,
                                            const float* __restrict__ gv,
                                            const float* __restrict__ bln,
                                            const float* __restrict__ qkb) {
    int h = blockIdx.x & 7, b4 = blockIdx.x >> 3;    // grid 128
    __shared__ float qs[4][64];
    __shared__ float red[4][256];
    int tid = threadIdx.x;
    {
        int bb = tid >> 6, j = tid & 63;
        qs[bb][j] = g_query[(b4*4 + bb)*512 + h*64 + j];
    }
    __syncthreads();
    int d = tid * 4;
    float4 acc[4];
#pragma unroll
    for (int bb = 0; bb < 4; bb++) acc[bb] = make_float4(0.f,0.f,0.f,0.f);
#pragma unroll 4
    for (int j = 0; j < 64; j++) {
        float4 wv = *(const float4*)(qkw + (size_t)(h*64 + j)*1024 + d);
#pragma unroll
        for (int bb = 0; bb < 4; bb++) {
            float a = qs[bb][j];
            acc[bb].x = fmaf(wv.x, a, acc[bb].x);
            acc[bb].y = fmaf(wv.y, a, acc[bb].y);
            acc[bb].z = fmaf(wv.z, a, acc[bb].z);
            acc[bb].w = fmaf(wv.w, a, acc[bb].w);
        }
    }
    float4 gg = *(const float4*)(gv + d);
    float4 bl = *(const float4*)(bln + d);
    float swp[4], cbp[4];
#pragma unroll
    for (int bb = 0; bb < 4; bb++) {
        float4 w4v;
        w4v.x = acc[bb].x * gg.x * 0.125f;
        w4v.y = acc[bb].y * gg.y * 0.125f;
        w4v.z = acc[bb].z * gg.z * 0.125f;
        w4v.w = acc[bb].w * gg.w * 0.125f;
        *(float4*)(g_w + ((size_t)((b4*4 + bb)*8 + h))*1024 + d) = w4v;
        swp[bb] = w4v.x + w4v.y + w4v.z + w4v.w;
        float c = acc[bb].x*bl.x + acc[bb].y*bl.y + acc[bb].z*bl.z + acc[bb].w*bl.w;
        if (tid < 64) c = fmaf(qs[bb][tid], qkb[h*64 + tid], c);
        cbp[bb] = c;
    }
#pragma unroll
    for (int bb = 0; bb < 4; bb++) red[bb][tid] = swp[bb];
    __syncthreads();
    for (int s = 128; s > 0; s >>= 1) {
        if (tid < s) {
#pragma unroll
            for (int bb = 0; bb < 4; bb++) red[bb][tid] += red[bb][tid + s];
        }
        __syncthreads();
    }
    if (tid < 4) g_sw[(b4*4 + tid)*8 + h] = red[tid][0];
    __syncthreads();
#pragma unroll
    for (int bb = 0; bb < 4; bb++) red[bb][tid] = cbp[bb];
    __syncthreads();
    for (int s = 128; s > 0; s >>= 1) {
        if (tid < s) {
#pragma unroll
            for (int bb = 0; bb < 4; bb++) red[bb][tid] += red[bb][tid + s];
        }
        __syncthreads();
    }
    if (tid < 4) g_cb[(b4*4 + tid)*8 + h] = red[tid][0] * 0.125f;
}

// ------- C: big score pass; scalar FMA; butterfly reduce (R8 version) -------
__global__ void __launch_bounds__(256) kC(const float* __restrict__ x) {
    int b = blockIdx.x >> 5, tc = blockIdx.x & 31;   // grid 2048
    __shared__ float4 ws4[2048];                      // 8 heads x 1024 floats
    __shared__ float sm[32], sr[32], sb2[32], ssw[8], scb[8];
    int tid = threadIdx.x;
    const float4* w4 = (const float4*)(g_w + (size_t)b*8192);
#pragma unroll
    for (int i = 0; i < 8; i++) ws4[tid + i*256] = w4[tid + i*256];
    int n0 = tc * 32;
    if (tid < 32) {
        sm[tid]  = g_mean [b*1024 + n0 + tid];
        sr[tid]  = g_rstd [b*1024 + n0 + tid];
        sb2[tid] = g_biasg[b*1024 + n0 + tid];
    } else if (tid < 40) {
        ssw[tid-32] = g_sw[b*8 + tid-32];
        scb[tid-32] = g_cb[b*8 + tid-32];
    }
    __syncthreads();
    int warp = tid >> 5, lane = tid & 31;
    int t0 = n0 + warp*4;
    const float4* X4 = (const float4*)x + ((size_t)b*1024 + t0)*256;
    float vals[32];                                   // vals[h*4+tt]
#pragma unroll
    for (int i = 0; i < 32; i++) vals[i] = 0.f;
#pragma unroll
    for (int c = 0; c < 8; c++) {
        float4 xv[4];
#pragma unroll
        for (int tt = 0; tt < 4; tt++) xv[tt] = X4[(size_t)tt*256 + lane + c*32];
#pragma unroll
        for (int h = 0; h < 8; h++) {
            float4 wv = ws4[h*256 + lane + c*32];
#pragma unroll
            for (int tt = 0; tt < 4; tt++) {
                float a = vals[h*4 + tt];
                a = fmaf(xv[tt].x, wv.x, a);
                a = fmaf(xv[tt].y, wv.y, a);
                a = fmaf(xv[tt].z, wv.z, a);
                a = fmaf(xv[tt].w, wv.w, a);
                vals[h*4 + tt] = a;
            }
        }
    }
    // multi-value butterfly: 32 values -> 1 per lane (index = bitrev5(lane))
#pragma unroll
    for (int s = 0; s < 5; s++) {
        int o = 1 << s;
        int nv = 32 >> s;
        int half = nv >> 1;
#pragma unroll
        for (int j = 0; j < 32; j++) {
            if (j < nv) vals[j] += __shfl_xor_sync(FULLM, vals[j], o);
        }
#pragma unroll
        for (int j = 0; j < 16; j++) {
            if (j < half) vals[j] = (lane & o) ? vals[j + half] : vals[j];
        }
    }
    int rev = ((lane & 1) << 4) | ((lane & 2) << 2) | (lane & 4)
            | ((lane & 8) >> 2) | ((lane & 16) >> 4);
    int h  = rev >> 2;
    int tt = rev & 3;
    int tloc = warp*4 + tt;
    float score = (vals[0] - sm[tloc]*ssw[h]) * sr[tloc] + scb[h] + sb2[tloc];
    g_scores[(size_t)(b*8 + h)*1024 + n0 + tloc] = score;
}

// ------- DE1 (fused kD+kE1): one block per (b,h). Warp 0 does register
// top-32 + softmax renorm; all warps then gather z. -------
__global__ void __launch_bounds__(256) kDE1(const float* __restrict__ x,
                                            const float* __restrict__ gv,
                                            const float* __restrict__ bln) {
    int bh = blockIdx.x, b = bh >> 3;                // grid 512
    __shared__ int   sidx[32];
    __shared__ float sal [32];
    __shared__ float sAP[2];
    int tid = threadIdx.x;
    int lane = tid & 31;
    if (tid < 32) {
        const float* src = g_scores + (size_t)bh*1024;
        float v[32];
#pragma unroll
        for (int j = 0; j < 32; j++) v[j] = src[j*32 + lane];  // n = j*32 + lane
        unsigned taken = 0u;
        float cm = v[0]; int cj = 0;
#pragma unroll
        for (int j = 1; j < 32; j++) if (v[j] > cm) { cm = v[j]; cj = j; }
        float keep_v = NEG_INF; int keep_n = 0;
        for (int k = 0; k < 32; k++) {
            float m = cm; int mn = (cj << 5) | lane;
#pragma unroll
            for (int o = 16; o > 0; o >>= 1) {
                float om = __shfl_xor_sync(FULLM, m,  o);
                int   on = __shfl_xor_sync(FULLM, mn, o);
                if (om > m || (om == m && on < mn)) { m = om; mn = on; }
            }
            if (lane == k) { keep_v = m; keep_n = mn; }
            if ((mn & 31) == lane) taken |= 1u << (mn >> 5);
            cm = NEG_INF; cj = 0;
#pragma unroll
            for (int j = 0; j < 32; j++) {
                bool ok = ((taken >> j) & 1u) == 0u;
                if (ok && v[j] > cm) { cm = v[j]; cj = j; }
            }
        }
        float M = __shfl_sync(FULLM, keep_v, 0);
        float zs = 0.f;
#pragma unroll
        for (int j = 0; j < 32; j++) zs += expf(v[j] - M);
#pragma unroll
        for (int o = 16; o > 0; o >>= 1) zs += __shfl_xor_sync(FULLM, zs, o);
        float e = expf(keep_v - M);
        float Se = e;
#pragma unroll
        for (int o = 16; o > 0; o >>= 1) Se += __shfl_xor_sync(FULLM, Se, o);
        float p = e / (Se + 1e-9f * zs);
        float alpha = p * g_rstd[b*1024 + keep_n];
        sidx[lane] = keep_n;
        sal [lane] = alpha;
        float Av = alpha * g_mean[b*1024 + keep_n];
        float Pv = p;
#pragma unroll
        for (int o = 16; o > 0; o >>= 1) {
            Av += __shfl_xor_sync(FULLM, Av, o);
            Pv += __shfl_xor_sync(FULLM, Pv, o);
        }
        if (lane == 0) { sAP[0] = Av; sAP[1] = Pv; }
    }
    __syncthreads();
    int d = tid * 4;
    float4 acc = make_float4(0.f, 0.f, 0.f, 0.f);
#pragma unroll 8
    for (int k = 0; k < 32; k++) {
        float4 xv = *(const float4*)(x + ((size_t)(b*1024 + sidx[k]))*1024 + d);
        float a = sal[k];
        acc.x = fmaf(xv.x, a, acc.x);
        acc.y = fmaf(xv.y, a, acc.y);
        acc.z = fmaf(xv.z, a, acc.z);
        acc.w = fmaf(xv.w, a, acc.w);
    }
    float A = sAP[0], P = sAP[1];
    float4 gg = *(const float4*)(gv + d);
    float4 bb = *(const float4*)(bln + d);
    float4 z;
    z.x = gg.x * (acc.x - A) + bb.x * P;
    z.y = gg.y * (acc.y - A) + bb.y * P;
    z.z = gg.z * (acc.z - A) + bb.z * P;
    z.w = gg.w * (acc.w - A) + bb.w * P;
    *(float4*)(g_Z + (size_t)bh*1024 + d) = z;
    if (tid == 0) {
        // stash P for kE2 (reuse g_cb slot is unsafe; use g_sw? no — dedicated)
        g_scores[(size_t)bh*1024] = g_scores[(size_t)bh*1024]; // no-op keep
    }
    if (tid == 32) g_sw[bh] = P;   // g_sw no longer needed after kC: reuse as P store
}

// ------- E2: y[b,h,j] = v_w_h[j].z[b,h] + v_b*P ; relu(+skip) -------
__global__ void __launch_bounds__(256) kE2(const float* __restrict__ vw,
                                           const float* __restrict__ vb) {
    int h = blockIdx.x & 7, g4 = blockIdx.x >> 3;    // grid 128
    __shared__ float zs[4][1024];
    __shared__ float sP[4];
    int tid = threadIdx.x;
    for (int i = tid; i < 4096; i += 256) {
        int bb = i >> 10, dd = i & 1023;
        zs[bb][dd] = g_Z[((size_t)((g4*4 + bb)*8 + h))*1024 + dd];
    }
    if (tid < 4) sP[tid] = g_sw[(g4*4 + tid)*8 + h];   // P stashed by kDE1
    __syncthreads();
    int warp = tid >> 5, lane = tid & 31;
#pragma unroll
    for (int t = 0; t < 8; t++) {
        int j = warp + t*8;
        const float* vr = vw + (size_t)(h*64 + j)*1024;
        float acc[4];
#pragma unroll
        for (int bb = 0; bb < 4; bb++) acc[bb] = 0.f;
#pragma unroll
        for (int c = 0; c < 8; c++) {
            int d = c*128 + lane*4;
            float4 wv = *(const float4*)(vr + d);
#pragma unroll
            for (int bb = 0; bb < 4; bb++) {
                float4 zv = *(const float4*)(&zs[bb][d]);
                acc[bb] = fmaf(wv.x, zv.x, acc[bb]);
                acc[bb] = fmaf(wv.y, zv.y, acc[bb]);
                acc[bb] = fmaf(wv.z, zv.z, acc[bb]);
                acc[bb] = fmaf(wv.w, zv.w, acc[bb]);
            }
        }
#pragma unroll
        for (int bb = 0; bb < 4; bb++)
#pragma unroll
            for (int o = 16; o > 0; o >>= 1)
                acc[bb] += __shfl_xor_sync(FULLM, acc[bb], o);
        if (lane == 0) {
            int q = h*64 + j;
            float vbq = vb[q];
#pragma unroll
            for (int bb = 0; bb < 4; bb++) {
                int b = g4*4 + bb;
                float y = acc[bb] + vbq * sP[bb] + g_skip[b*512 + q];
                g_relu[b*512 + q] = fmaxf(y, 0.f);
            }
        }
    }
}

// ------- Mw: fold out_w/fc_w: Mw[c][q] = sum_q' fc_w[c][q'] out_w[q'][q] -------
__global__ void __launch_bounds__(512) kMw(const float* __restrict__ ow,
                                           const float* __restrict__ ob,
                                           const float* __restrict__ fcw,
                                           const float* __restrict__ fcb) {
    int c = blockIdx.x;            // 2 blocks
    int q = threadIdx.x;           // 512 threads
    __shared__ float fr[512];
    __shared__ float red[512];
    fr[q] = fcw[c*512 + q];
    __syncthreads();
    float acc = 0.f;
#pragma unroll 8
    for (int qp = 0; qp < 512; qp++)
        acc = fmaf(fr[qp], ow[(size_t)qp*512 + q], acc);
    g_Mw[c*512 + q] = acc;
    red[q] = fr[q] * ob[q];
    __syncthreads();
    for (int s = 256; s > 0; s >>= 1) {
        if (q < s) red[q] += red[q+s];
        __syncthreads();
    }
    if (q == 0) g_Mb[c] = red[0] + fcb[c];
}

// ------- F: final [64,2] = relu @ Mw^T + Mb -------
__global__ void __launch_bounds__(128) kF(float* __restrict__ out) {
    int b = blockIdx.x, tid = threadIdx.x;     // 128 threads
    int warp = tid >> 5, lane = tid & 31;
    __shared__ float p0[4], p1[4];
    float s0 = 0.f, s1 = 0.f;
#pragma unroll
    for (int i = 0; i < 4; i++) {
        int q = tid + i*128;
        float rv = g_relu[b*512 + q];
        s0 = fmaf(rv, g_Mw[q],       s0);
        s1 = fmaf(rv, g_Mw[512 + q], s1);
    }
#pragma unroll
    for (int o = 16; o > 0; o >>= 1) {
        s0 += __shfl_xor_sync(FULLM, s0, o);
        s1 += __shfl_xor_sync(FULLM, s1, o);
    }
    if (lane == 0) { p0[warp] = s0; p1[warp] = s1; }
    __syncthreads();
    if (tid == 0) {
        out[b*2 + 0] = p0[0] + p0[1] + p0[2] + p0[3] + g_Mb[0];
        out[b*2 + 1] = p1[0] + p1[1] + p1[2] + p1[3] + g_Mb[1];
    }
}

extern "C" void kernel_launch(void* const* d_in, const int* in_sizes, int n_in,
                              void* d_out, int out_size) {
    const float* x        = (const float*)d_in[0];
    const float* scorer_w = (const float*)d_in[1];
    const float* scorer_b = (const float*)d_in[2];
    const float* ln_g     = (const float*)d_in[3];
    const float* ln_b     = (const float*)d_in[4];
    const float* qk_w     = (const float*)d_in[5];
    const float* qk_b     = (const float*)d_in[6];
    const float* v_w      = (const float*)d_in[7];
    const float* v_b      = (const float*)d_in[8];
    const float* skip_w   = (const float*)d_in[9];
    const float* skip_b   = (const float*)d_in[10];
    const float* out_w    = (const float*)d_in[11];
    const float* out_b    = (const float*)d_in[12];
    const float* fc_w     = (const float*)d_in[13];
    const float* fc_b     = (const float*)d_in[14];
    const float* ub       = (const float*)d_in[15];
    const int*   rel_idx  = (const int*)  d_in[16];
    float* out = (float*)d_out;
    (void)in_sizes; (void)n_in; (void)out_size;

    kMw <<<2,    512>>>(out_w, out_b, fc_w, fc_b);    // fused tail matrix
    kA  <<<8192, 256>>>(x, scorer_w, scorer_b);       // pass 1 over x
    kB1 <<<64,   256>>>(x, ln_g, ln_b, ub, rel_idx);
    kQS <<<1024, 256>>>(qk_w, qk_b, skip_w, skip_b);  // query + skip in one launch
    kB34<<<128,  256>>>(qk_w, ln_g, ln_b, qk_b);      // u -> w, sw, cb fused
    kC  <<<2048, 256>>>(x);                           // scores (pass 2 over x)
    kDE1<<<512,  256>>>(x, ln_g, ln_b);               // top-32 + renorm + gather z
    kE2 <<<128,  256>>>(v_w, v_b);                    // y = v_w.z, relu(+skip)
    kF  <<<64,   128>>>(out);                         // final [64,2]
}